// round 10
// baseline (speedup 1.0000x reference)
#include <cuda_runtime.h>
#include <math.h>

#define N_NODES 100000
#define N_EDGES 800000
#define F_IN    128
#define HID     512
#define N_CLS   40
#define BN_EPS  1e-5f

// ---------------- scratch (static device globals; no allocation) ----------------
__device__ int    g_is64;
__device__ float  g_deg[N_NODES];
__device__ float  g_dinv[N_NODES];
__device__ int    g_src[N_EDGES];
__device__ int    g_dst[N_EDGES];
__device__ float  g_norm[N_EDGES];
__device__ float4 g_h4[(size_t)N_NODES * HID / 4];    // GEMM output
__device__ float4 g_agg4[(size_t)N_NODES * HID / 4];  // aggregation accumulator
__device__ float4 g_act4[(size_t)N_NODES * HID / 4];  // layer-1 activation
__device__ float  g_sum[HID];
__device__ float  g_sumsq[HID];

// ---------------- edge dtype detection ----------------
// int64 edges (values < 2^31): every odd 32-bit word is 0.
// int32 edges: odd words are random node ids, virtually never all zero.
__global__ void k_detect_dtype(const int* __restrict__ ei32) {
    if (threadIdx.x == 0 && blockIdx.x == 0) {
        int nonzero = 0;
        for (int i = 0; i < 1024; i++) {
            if (ei32[2 * i + 1] != 0) nonzero++;
        }
        g_is64 = (nonzero == 0) ? 1 : 0;
    }
}

// ---------------- degree / dinv / edge preprocessing ----------------
__global__ void k_deg_init() {
    int i = blockIdx.x * blockDim.x + threadIdx.x;
    if (i < N_NODES) g_deg[i] = 1.0f;  // self loop
}

__global__ void k_deg_count(const void* __restrict__ ei) {
    int e = blockIdx.x * blockDim.x + threadIdx.x;
    if (e >= N_EDGES) return;
    int s, d;
    if (g_is64) {
        const long long* p = (const long long*)ei;
        s = (int)p[e];
        d = (int)p[N_EDGES + e];
    } else {
        const int* p = (const int*)ei;
        s = p[e];
        d = p[N_EDGES + e];
    }
    // defensive clamp: never let a bad index become a wild atomic
    if (s < 0 || s >= N_NODES) s = 0;
    if (d < 0 || d >= N_NODES) d = 0;
    g_src[e] = s;
    g_dst[e] = d;
    atomicAdd(&g_deg[d], 1.0f);
}

__global__ void k_dinv() {
    int i = blockIdx.x * blockDim.x + threadIdx.x;
    if (i < N_NODES) g_dinv[i] = rsqrtf(g_deg[i]);
}

__global__ void k_edge_norm() {
    int e = blockIdx.x * blockDim.x + threadIdx.x;
    if (e < N_EDGES) g_norm[e] = g_dinv[g_src[e]] * g_dinv[g_dst[e]];
}

// ---------------- SGEMM: g_h[M,N] = A[M,K] @ W[K,N] ----------------
// A is either an external pointer (inputs / d_out) or g_act (use_act=1).
// 128x64 block tile, BK=16, 8x4 per thread, 256 threads.
#define BM 128
#define BN 64
#define BK 16
#define TM 8
#define TN 4

__global__ void k_sgemm(const float* __restrict__ A_ext, int use_act,
                        const float* __restrict__ W,
                        int M, int K, int N) {
    const float* A = use_act ? (const float*)g_act4 : A_ext;
    float* C = (float*)g_h4;

    __shared__ float As[BK][BM];   // A tile transposed: As[k][m]
    __shared__ float Bs[BK][BN];

    const int block_row = blockIdx.y * BM;
    const int block_col = blockIdx.x * BN;
    const int tid = threadIdx.x;            // 0..255
    const int tx = tid % (BN / TN);         // 0..15
    const int ty = tid / (BN / TN);         // 0..15

    float acc[TM][TN];
#pragma unroll
    for (int i = 0; i < TM; i++)
#pragma unroll
        for (int j = 0; j < TN; j++) acc[i][j] = 0.0f;

    for (int k0 = 0; k0 < K; k0 += BK) {
#pragma unroll
        for (int i = tid; i < BM * BK; i += 256) {
            int m = i / BK, k = i % BK;
            int gr = block_row + m;
            As[k][m] = (gr < M) ? A[(size_t)gr * K + (k0 + k)] : 0.0f;
        }
#pragma unroll
        for (int i = tid; i < BK * BN; i += 256) {
            int k = i / BN, n = i % BN;
            int gc = block_col + n;
            Bs[k][n] = (gc < N) ? W[(size_t)(k0 + k) * N + gc] : 0.0f;
        }
        __syncthreads();

#pragma unroll
        for (int k = 0; k < BK; k++) {
            float a[TM], b[TN];
#pragma unroll
            for (int i = 0; i < TM; i++) a[i] = As[k][ty * TM + i];
#pragma unroll
            for (int j = 0; j < TN; j++) b[j] = Bs[k][tx * TN + j];
#pragma unroll
            for (int i = 0; i < TM; i++)
#pragma unroll
                for (int j = 0; j < TN; j++) acc[i][j] = fmaf(a[i], b[j], acc[i][j]);
        }
        __syncthreads();
    }

#pragma unroll
    for (int i = 0; i < TM; i++) {
        int r = block_row + ty * TM + i;
        if (r >= M) continue;
#pragma unroll
        for (int j = 0; j < TN; j++) {
            int c = block_col + tx * TN + j;
            if (c < N) C[(size_t)r * N + c] = acc[i][j];
        }
    }
}

// ---------------- aggregation ----------------
// g_agg = g_h * dinv^2 + bias  (self-loop + bias; accumulator init). float4.
__global__ void k_self_init(const float* __restrict__ bias, int O) {
    int nv = O >> 2;
    size_t idx = (size_t)blockIdx.x * blockDim.x + threadIdx.x;
    size_t total = (size_t)N_NODES * nv;
    if (idx >= total) return;
    int node = (int)(idx / nv);
    int f4 = (int)(idx % nv);
    float di = g_dinv[node];
    float sc = di * di;
    float4 h = g_h4[idx];
    const float* b = bias + f4 * 4;
    float4 r;
    r.x = h.x * sc + b[0];
    r.y = h.y * sc + b[1];
    r.z = h.z * sc + b[2];
    r.w = h.w * sc + b[3];
    g_agg4[idx] = r;
}

// one warp per edge: g_agg[dst] += g_h[src] * norm, via single float4 atomics
__global__ void k_edge_agg(int O) {
    int gid = blockIdx.x * blockDim.x + threadIdx.x;
    int e = gid >> 5;
    int lane = gid & 31;
    if (e >= N_EDGES) return;
    int s = g_src[e];
    int d = g_dst[e];
    float norm = g_norm[e];
    int nv = O >> 2;
    const float4* hs = g_h4 + (size_t)s * nv;
    float4* ad = g_agg4 + (size_t)d * nv;
    for (int f = lane; f < nv; f += 32) {
        float4 v = hs[f];
        float4 u;
        u.x = v.x * norm; u.y = v.y * norm; u.z = v.z * norm; u.w = v.w * norm;
        atomicAdd(&ad[f], u);   // RED.E.ADD.F32.128 on sm_90+
    }
}

// ---------------- batch norm ----------------
__global__ void k_zero_sums(int O) {
    int c = blockIdx.x * blockDim.x + threadIdx.x;
    if (c < O) { g_sum[c] = 0.0f; g_sumsq[c] = 0.0f; }
}

__global__ void k_bn_reduce(int O) {
    int c = blockIdx.x * blockDim.x + threadIdx.x;
    if (c >= O) return;
    const float* agg = (const float*)g_agg4;
    float s = 0.0f, ss = 0.0f;
    for (int r = blockIdx.y; r < N_NODES; r += gridDim.y) {
        float v = agg[(size_t)r * O + c];
        s += v;
        ss += v * v;
    }
    atomicAdd(&g_sum[c], s);
    atomicAdd(&g_sumsq[c], ss);
}

// y = BN(g_agg) [+ReLU]; y is d_out region (use_act=0) or g_act (use_act=1). float4.
__global__ void k_bn_apply(float* __restrict__ y_ext, int use_act,
                           const float* __restrict__ gamma,
                           const float* __restrict__ beta,
                           int O, int do_relu) {
    float4* y = use_act ? g_act4 : (float4*)y_ext;
    int nv = O >> 2;
    size_t idx = (size_t)blockIdx.x * blockDim.x + threadIdx.x;
    size_t total = (size_t)N_NODES * nv;
    if (idx >= total) return;
    int f4 = (int)(idx % nv);
    int c = f4 * 4;
    float4 v = g_agg4[idx];
    float4 r;
    const float inv_n = 1.0f / N_NODES;
#pragma unroll
    for (int j = 0; j < 4; j++) {
        float mu = g_sum[c + j] * inv_n;
        float var = g_sumsq[c + j] * inv_n - mu * mu;
        float* vp = (j == 0) ? &v.x : (j == 1) ? &v.y : (j == 2) ? &v.z : &v.w;
        float* rp = (j == 0) ? &r.x : (j == 1) ? &r.y : (j == 2) ? &r.z : &r.w;
        float o = gamma[c + j] * (*vp - mu) * rsqrtf(var + BN_EPS) + beta[c + j];
        if (do_relu) o = fmaxf(o, 0.0f);
        *rp = o;
    }
    y[idx] = r;
}

// ---------------- launch ----------------
static inline int cdiv(long long a, long long b) { return (int)((a + b - 1) / b); }

extern "C" void kernel_launch(void* const* d_in, const int* in_sizes, int n_in,
                              void* d_out, int out_size) {
    const float* x = (const float*)d_in[0];
    const void* ei = d_in[1];          // int32 or int64 — detected on device
    const float* W1 = (const float*)d_in[2];
    const float* b1 = (const float*)d_in[3];
    const float* g1 = (const float*)d_in[4];
    const float* be1 = (const float*)d_in[5];
    const float* W2 = (const float*)d_in[6];
    const float* b2 = (const float*)d_in[7];
    const float* g2 = (const float*)d_in[8];
    const float* be2 = (const float*)d_in[9];
    const float* W3 = (const float*)d_in[10];
    const float* b3 = (const float*)d_in[11];
    const float* g3 = (const float*)d_in[12];
    const float* be3 = (const float*)d_in[13];

    float* out_logits = (float*)d_out;                               // [N, 40]
    float* out_x6 = (float*)d_out + (size_t)N_NODES * N_CLS;         // [N, 512]

    const int T = 256;

    // dtype detection + degrees + per-edge norm
    k_detect_dtype<<<1, 32>>>((const int*)ei);
    k_deg_init<<<cdiv(N_NODES, T), T>>>();
    k_deg_count<<<cdiv(N_EDGES, T), T>>>(ei);
    k_dinv<<<cdiv(N_NODES, T), T>>>();
    k_edge_norm<<<cdiv(N_EDGES, T), T>>>();

    dim3 gemm_grid_h(HID / BN, cdiv(N_NODES, BM));
    dim3 gemm_grid_c(cdiv(N_CLS, BN), cdiv(N_NODES, BM));

    size_t totH4 = (size_t)N_NODES * (HID / 4);
    size_t totC4 = (size_t)N_NODES * (N_CLS / 4);
    int edge_blocks = cdiv((long long)N_EDGES * 32, T);

    // ---- Layer 1: x @ W1 -> g_h ; aggregate -> g_agg ; BN+ReLU -> g_act
    k_sgemm<<<gemm_grid_h, T>>>(x, 0, W1, N_NODES, F_IN, HID);
    k_self_init<<<cdiv(totH4, T), T>>>(b1, HID);
    k_edge_agg<<<edge_blocks, T>>>(HID);
    k_zero_sums<<<cdiv(HID, T), T>>>(HID);
    {
        dim3 rg(cdiv(HID, T), 128);
        k_bn_reduce<<<rg, T>>>(HID);
    }
    k_bn_apply<<<cdiv(totH4, T), T>>>(nullptr, 1, g1, be1, HID, 1);

    // ---- Layer 2: g_act @ W2 -> g_h ; aggregate ; BN+ReLU -> x6 (in d_out)
    k_sgemm<<<gemm_grid_h, T>>>(nullptr, 1, W2, N_NODES, HID, HID);
    k_self_init<<<cdiv(totH4, T), T>>>(b2, HID);
    k_edge_agg<<<edge_blocks, T>>>(HID);
    k_zero_sums<<<cdiv(HID, T), T>>>(HID);
    {
        dim3 rg(cdiv(HID, T), 128);
        k_bn_reduce<<<rg, T>>>(HID);
    }
    k_bn_apply<<<cdiv(totH4, T), T>>>(out_x6, 0, g2, be2, HID, 1);

    // ---- Layer 3: x6 @ W3 -> g_h[:, :40] ; aggregate ; BN -> logits
    k_sgemm<<<gemm_grid_c, T>>>(out_x6, 0, W3, N_NODES, HID, N_CLS);
    k_self_init<<<cdiv(totC4, T), T>>>(b3, N_CLS);
    k_edge_agg<<<edge_blocks, T>>>(N_CLS);
    k_zero_sums<<<cdiv(N_CLS, T), T>>>(N_CLS);
    {
        dim3 rg(cdiv(N_CLS, T), 128);
        k_bn_reduce<<<rg, T>>>(N_CLS);
    }
    k_bn_apply<<<cdiv(totC4, T), T>>>(out_logits, 0, g3, be3, N_CLS, 0);
}

// round 12
// speedup vs baseline: 1.5517x; 1.5517x over previous
#include <cuda_runtime.h>
#include <math.h>

#define N_NODES 100000
#define N_EDGES 800000
#define F_IN    128
#define HID     512
#define N_CLS   40
#define BN_EPS  1e-5f
#define NBLK_SCAN 391   // cdiv(N_NODES, 256)

// ---------------- scratch (static device globals; no allocation) ----------------
__device__ int    g_is64;
__device__ float  g_deg[N_NODES];
__device__ float  g_dinv[N_NODES];
__device__ int    g_cnt[N_NODES];        // integer degree (no self loop)
__device__ int    g_scan[N_NODES];       // block-inclusive scan of cnt
__device__ int    g_rowstart[N_NODES];   // CSR row offsets
__device__ int    g_cursor[N_NODES];     // fill cursors
__device__ int    g_bsum[NBLK_SCAN];     // per-block sums
__device__ int    g_boff[NBLK_SCAN];     // exclusive block offsets
__device__ int    g_srcb[N_EDGES];       // raw src (decoded)
__device__ int    g_dstb[N_EDGES];       // raw dst (decoded)
__device__ int    g_csrc[N_EDGES];       // CSR: src per slot
__device__ float  g_cnorm[N_EDGES];      // CSR: norm per slot
__device__ float4 g_h4[(size_t)N_NODES * HID / 4];    // GEMM output
__device__ float4 g_agg4[(size_t)N_NODES * HID / 4];  // aggregation result
__device__ float4 g_act4[(size_t)N_NODES * HID / 4];  // layer-1 activation
__device__ float  g_sum[HID];
__device__ float  g_sumsq[HID];

// ---------------- edge dtype detection ----------------
__global__ void k_detect_dtype(const int* __restrict__ ei32) {
    if (threadIdx.x == 0 && blockIdx.x == 0) {
        int nonzero = 0;
        for (int i = 0; i < 1024; i++)
            if (ei32[2 * i + 1] != 0) nonzero++;
        g_is64 = (nonzero == 0) ? 1 : 0;
    }
}

// ---------------- degree counting ----------------
__global__ void k_deg_init() {
    int i = blockIdx.x * blockDim.x + threadIdx.x;
    if (i < N_NODES) { g_deg[i] = 1.0f; g_cnt[i] = 0; }  // +1 self loop (float deg)
}

__global__ void k_deg_count(const void* __restrict__ ei) {
    int e = blockIdx.x * blockDim.x + threadIdx.x;
    if (e >= N_EDGES) return;
    int s, d;
    if (g_is64) {
        const long long* p = (const long long*)ei;
        s = (int)p[e];
        d = (int)p[N_EDGES + e];
    } else {
        const int* p = (const int*)ei;
        s = p[e];
        d = p[N_EDGES + e];
    }
    if (s < 0 || s >= N_NODES) s = 0;   // defensive: wrong answer beats a trap
    if (d < 0 || d >= N_NODES) d = 0;
    g_srcb[e] = s;
    g_dstb[e] = d;
    atomicAdd(&g_deg[d], 1.0f);
    atomicAdd(&g_cnt[d], 1);
}

__global__ void k_dinv() {
    int i = blockIdx.x * blockDim.x + threadIdx.x;
    if (i < N_NODES) g_dinv[i] = rsqrtf(g_deg[i]);
}

// ---------------- prefix scan (3 kernels) ----------------
__global__ void k_scan1() {
    __shared__ int wsum[8];
    int i = blockIdx.x * 256 + threadIdx.x;
    int lane = threadIdx.x & 31;
    int wid = threadIdx.x >> 5;
    int v = (i < N_NODES) ? g_cnt[i] : 0;
    // warp inclusive scan
#pragma unroll
    for (int o = 1; o < 32; o <<= 1) {
        int n = __shfl_up_sync(0xFFFFFFFFu, v, o);
        if (lane >= o) v += n;
    }
    if (lane == 31) wsum[wid] = v;
    __syncthreads();
    if (wid == 0) {
        int w = (lane < 8) ? wsum[lane] : 0;
#pragma unroll
        for (int o = 1; o < 8; o <<= 1) {
            int n = __shfl_up_sync(0xFFFFFFFFu, w, o);
            if (lane >= o) w += n;
        }
        if (lane < 8) wsum[lane] = w;
    }
    __syncthreads();
    if (wid > 0) v += wsum[wid - 1];
    if (i < N_NODES) g_scan[i] = v;
    if (threadIdx.x == 255) g_bsum[blockIdx.x] = v;
}

__global__ void k_scan2() {
    __shared__ int s[NBLK_SCAN];
    int t = threadIdx.x;
    if (t < NBLK_SCAN) s[t] = g_bsum[t];
    __syncthreads();
    if (t == 0) {
        int run = 0;
        for (int b = 0; b < NBLK_SCAN; b++) {
            g_boff[b] = run;
            run += s[b];
        }
    }
}

__global__ void k_scan3() {
    int i = blockIdx.x * 256 + threadIdx.x;
    if (i >= N_NODES) return;
    int rs = g_boff[blockIdx.x] + g_scan[i] - g_cnt[i];  // exclusive
    g_rowstart[i] = rs;
    g_cursor[i] = rs;
}

// ---------------- CSR build ----------------
__global__ void k_build_csr() {
    int e = blockIdx.x * blockDim.x + threadIdx.x;
    if (e >= N_EDGES) return;
    int s = g_srcb[e];
    int d = g_dstb[e];
    int pos = atomicAdd(&g_cursor[d], 1);
    g_csrc[pos] = s;
    g_cnorm[pos] = g_dinv[s] * g_dinv[d];
}

// ---------------- SGEMM: g_h[M,N] = A[M,K] @ W[K,N] ----------------
// 128x128 tile, BK=8, 8x8 per thread, 256 threads, float4 I/O.
#define BM 128
#define BN 128
#define BK 8

__global__ void __launch_bounds__(256) k_sgemm(
        const float* __restrict__ A_ext, int use_act,
        const float* __restrict__ W, int M, int K, int N) {
    const float* A = use_act ? (const float*)g_act4 : A_ext;
    float* C = (float*)g_h4;

    __shared__ float As[BK][BM];
    __shared__ float Bs[BK][BN];

    const int tid = threadIdx.x;
    const int block_row = blockIdx.y * BM;
    const int block_col = blockIdx.x * BN;
    const int tx = tid % 16;            // col group (8 cols each)
    const int ty = tid / 16;            // row group (8 rows each)

    // A load: thread -> (row am, 4 cols at ak)
    const int am = tid >> 1;
    const int ak = (tid & 1) * 4;
    // B load: thread -> (row bk, 4 cols at bn)
    const int bk = tid >> 5;
    const int bn = (tid & 31) * 4;

    float acc[8][8];
#pragma unroll
    for (int i = 0; i < 8; i++)
#pragma unroll
        for (int j = 0; j < 8; j++) acc[i][j] = 0.0f;

    for (int k0 = 0; k0 < K; k0 += BK) {
        // A tile (coalesced float4; rows beyond M are zero)
        float4 av = make_float4(0.f, 0.f, 0.f, 0.f);
        int gr = block_row + am;
        if (gr < M) av = *(const float4*)(A + (size_t)gr * K + k0 + ak);
        As[ak + 0][am] = av.x;
        As[ak + 1][am] = av.y;
        As[ak + 2][am] = av.z;
        As[ak + 3][am] = av.w;

        // B tile (float4 when fully in-bounds, else guarded scalars)
        float4 bv;
        int gc = block_col + bn;
        if (gc + 3 < N) {
            bv = *(const float4*)(W + (size_t)(k0 + bk) * N + gc);
        } else {
            float t0 = (gc + 0 < N) ? W[(size_t)(k0 + bk) * N + gc + 0] : 0.f;
            float t1 = (gc + 1 < N) ? W[(size_t)(k0 + bk) * N + gc + 1] : 0.f;
            float t2 = (gc + 2 < N) ? W[(size_t)(k0 + bk) * N + gc + 2] : 0.f;
            float t3 = (gc + 3 < N) ? W[(size_t)(k0 + bk) * N + gc + 3] : 0.f;
            bv = make_float4(t0, t1, t2, t3);
        }
        *(float4*)&Bs[bk][bn] = bv;
        __syncthreads();

#pragma unroll
        for (int k = 0; k < BK; k++) {
            float a[8], b[8];
            *(float4*)&a[0] = *(const float4*)&As[k][ty * 8];
            *(float4*)&a[4] = *(const float4*)&As[k][ty * 8 + 4];
            *(float4*)&b[0] = *(const float4*)&Bs[k][tx * 8];
            *(float4*)&b[4] = *(const float4*)&Bs[k][tx * 8 + 4];
#pragma unroll
            for (int i = 0; i < 8; i++)
#pragma unroll
                for (int j = 0; j < 8; j++)
                    acc[i][j] = fmaf(a[i], b[j], acc[i][j]);
        }
        __syncthreads();
    }

#pragma unroll
    for (int i = 0; i < 8; i++) {
        int r = block_row + ty * 8 + i;
        if (r >= M) continue;
#pragma unroll
        for (int j0 = 0; j0 < 8; j0 += 4) {
            int c = block_col + tx * 8 + j0;
            if (c + 3 < N) {
                *(float4*)(C + (size_t)r * N + c) =
                    make_float4(acc[i][j0], acc[i][j0 + 1], acc[i][j0 + 2], acc[i][j0 + 3]);
            } else {
#pragma unroll
                for (int j = 0; j < 4; j++)
                    if (c + j < N) C[(size_t)r * N + c + j] = acc[i][j0 + j];
            }
        }
    }
}

// ---------------- CSR aggregation (fused self-loop + bias, no atomics) ------
// one warp per dst node; lane l covers float4 columns {l, l+32, l+64, l+96}
__global__ void k_agg_csr(const float* __restrict__ bias, int O) {
    int wg = (blockIdx.x * blockDim.x + threadIdx.x) >> 5;
    int lane = threadIdx.x & 31;
    if (wg >= N_NODES) return;
    const int d = wg;
    const int nv = O >> 2;
    const float di = g_dinv[d];
    const float sc = di * di;
    const int start = g_rowstart[d];
    const int cnt = g_cnt[d];
    const float4* b4 = (const float4*)bias;

    float4 acc[4];
    // init: self-loop term + bias
#pragma unroll
    for (int a = 0; a < 4; a++) {
        int f = lane + a * 32;
        if (f < nv) {
            float4 h = g_h4[(size_t)d * nv + f];
            float4 bb = b4[f];
            acc[a] = make_float4(h.x * sc + bb.x, h.y * sc + bb.y,
                                 h.z * sc + bb.z, h.w * sc + bb.w);
        }
    }
    // neighbors
    for (int j = 0; j < cnt; j++) {
        int s = g_csrc[start + j];
        float w = g_cnorm[start + j];
        const float4* hs = g_h4 + (size_t)s * nv;
#pragma unroll
        for (int a = 0; a < 4; a++) {
            int f = lane + a * 32;
            if (f < nv) {
                float4 v = hs[f];
                acc[a].x = fmaf(v.x, w, acc[a].x);
                acc[a].y = fmaf(v.y, w, acc[a].y);
                acc[a].z = fmaf(v.z, w, acc[a].z);
                acc[a].w = fmaf(v.w, w, acc[a].w);
            }
        }
    }
    float4* out = g_agg4 + (size_t)d * nv;
#pragma unroll
    for (int a = 0; a < 4; a++) {
        int f = lane + a * 32;
        if (f < nv) out[f] = acc[a];
    }
}

// ---------------- batch norm ----------------
__global__ void k_zero_sums(int O) {
    int c = blockIdx.x * blockDim.x + threadIdx.x;
    if (c < O) { g_sum[c] = 0.0f; g_sumsq[c] = 0.0f; }
}

__global__ void k_bn_reduce(int O) {
    int c = blockIdx.x * blockDim.x + threadIdx.x;
    if (c >= O) return;
    const float* agg = (const float*)g_agg4;
    float s = 0.0f, ss = 0.0f;
    for (int r = blockIdx.y; r < N_NODES; r += gridDim.y) {
        float v = agg[(size_t)r * O + c];
        s += v;
        ss += v * v;
    }
    atomicAdd(&g_sum[c], s);
    atomicAdd(&g_sumsq[c], ss);
}

__global__ void k_bn_apply(float* __restrict__ y_ext, int use_act,
                           const float* __restrict__ gamma,
                           const float* __restrict__ beta,
                           int O, int do_relu) {
    float4* y = use_act ? g_act4 : (float4*)y_ext;
    int nv = O >> 2;
    size_t idx = (size_t)blockIdx.x * blockDim.x + threadIdx.x;
    size_t total = (size_t)N_NODES * nv;
    if (idx >= total) return;
    int f4 = (int)(idx % nv);
    int c = f4 * 4;
    float4 v = g_agg4[idx];
    float4 r;
    const float inv_n = 1.0f / N_NODES;
#pragma unroll
    for (int j = 0; j < 4; j++) {
        float mu = g_sum[c + j] * inv_n;
        float var = g_sumsq[c + j] * inv_n - mu * mu;
        float* vp = (j == 0) ? &v.x : (j == 1) ? &v.y : (j == 2) ? &v.z : &v.w;
        float* rp = (j == 0) ? &r.x : (j == 1) ? &r.y : (j == 2) ? &r.z : &r.w;
        float o = gamma[c + j] * (*vp - mu) * rsqrtf(var + BN_EPS) + beta[c + j];
        if (do_relu) o = fmaxf(o, 0.0f);
        *rp = o;
    }
    y[idx] = r;
}

// ---------------- launch ----------------
static inline int cdiv(long long a, long long b) { return (int)((a + b - 1) / b); }

extern "C" void kernel_launch(void* const* d_in, const int* in_sizes, int n_in,
                              void* d_out, int out_size) {
    const float* x = (const float*)d_in[0];
    const void* ei = d_in[1];
    const float* W1 = (const float*)d_in[2];
    const float* b1 = (const float*)d_in[3];
    const float* g1 = (const float*)d_in[4];
    const float* be1 = (const float*)d_in[5];
    const float* W2 = (const float*)d_in[6];
    const float* b2 = (const float*)d_in[7];
    const float* g2 = (const float*)d_in[8];
    const float* be2 = (const float*)d_in[9];
    const float* W3 = (const float*)d_in[10];
    const float* b3 = (const float*)d_in[11];
    const float* g3 = (const float*)d_in[12];
    const float* be3 = (const float*)d_in[13];

    float* out_logits = (float*)d_out;                        // [N, 40]
    float* out_x6 = (float*)d_out + (size_t)N_NODES * N_CLS;  // [N, 512]

    const int T = 256;

    // preprocessing: dtype, degrees, CSR
    k_detect_dtype<<<1, 32>>>((const int*)ei);
    k_deg_init<<<cdiv(N_NODES, T), T>>>();
    k_deg_count<<<cdiv(N_EDGES, T), T>>>(ei);
    k_dinv<<<cdiv(N_NODES, T), T>>>();
    k_scan1<<<NBLK_SCAN, 256>>>();
    k_scan2<<<1, 512>>>();
    k_scan3<<<NBLK_SCAN, 256>>>();
    k_build_csr<<<cdiv(N_EDGES, T), T>>>();

    dim3 gemm_grid_h(HID / BN, cdiv(N_NODES, BM));     // (4, 782)
    dim3 gemm_grid_c(1, cdiv(N_NODES, BM));            // N=40 -> 1 col block

    size_t totH4 = (size_t)N_NODES * (HID / 4);
    size_t totC4 = (size_t)N_NODES * (N_CLS / 4);
    int agg_blocks = cdiv((long long)N_NODES * 32, T);

    // ---- Layer 1: x @ W1 -> g_h ; CSR agg -> g_agg ; BN+ReLU -> g_act
    k_sgemm<<<gemm_grid_h, T>>>(x, 0, W1, N_NODES, F_IN, HID);
    k_agg_csr<<<agg_blocks, T>>>(b1, HID);
    k_zero_sums<<<cdiv(HID, T), T>>>(HID);
    { dim3 rg(cdiv(HID, T), 128); k_bn_reduce<<<rg, T>>>(HID); }
    k_bn_apply<<<cdiv(totH4, T), T>>>(nullptr, 1, g1, be1, HID, 1);

    // ---- Layer 2: g_act @ W2 -> g_h ; CSR agg ; BN+ReLU -> x6 (in d_out)
    k_sgemm<<<gemm_grid_h, T>>>(nullptr, 1, W2, N_NODES, HID, HID);
    k_agg_csr<<<agg_blocks, T>>>(b2, HID);
    k_zero_sums<<<cdiv(HID, T), T>>>(HID);
    { dim3 rg(cdiv(HID, T), 128); k_bn_reduce<<<rg, T>>>(HID); }
    k_bn_apply<<<cdiv(totH4, T), T>>>(out_x6, 0, g2, be2, HID, 1);

    // ---- Layer 3: x6 @ W3 -> g_h[:, :40] ; CSR agg ; BN -> logits
    k_sgemm<<<gemm_grid_c, T>>>(out_x6, 0, W3, N_NODES, HID, N_CLS);
    k_agg_csr<<<agg_blocks, T>>>(b3, N_CLS);
    k_zero_sums<<<cdiv(N_CLS, T), T>>>(N_CLS);
    { dim3 rg(cdiv(N_CLS, T), 128); k_bn_reduce<<<rg, T>>>(N_CLS); }
    k_bn_apply<<<cdiv(totC4, T), T>>>(out_logits, 0, g3, be3, N_CLS, 0);
}

// round 15
// speedup vs baseline: 1.6320x; 1.0517x over previous
#include <cuda_runtime.h>
#include <math.h>

#define N_NODES 100000
#define N_EDGES 800000
#define F_IN    128
#define HID     512
#define N_CLS   40
#define BN_EPS  1e-5f
#define NBLK_SCAN 391   // cdiv(N_NODES, 256)

// ---------------- scratch (static device globals; no allocation) ----------------
__device__ int    g_is64;
__device__ float  g_deg[N_NODES];
__device__ float  g_dinv[N_NODES];
__device__ int    g_cnt[N_NODES];
__device__ int    g_scan[N_NODES];
__device__ int    g_rowstart[N_NODES];
__device__ int    g_cursor[N_NODES];
__device__ int    g_bsum[NBLK_SCAN];
__device__ int    g_boff[NBLK_SCAN];
__device__ int    g_srcb[N_EDGES];
__device__ int    g_dstb[N_EDGES];
__device__ int    g_csrc[N_EDGES];
__device__ float  g_cnorm[N_EDGES];
__device__ float4 g_h4[(size_t)N_NODES * HID / 4];    // GEMM output
__device__ float4 g_agg4[(size_t)N_NODES * HID / 4];  // aggregation result
__device__ float4 g_act4[(size_t)N_NODES * HID / 4];  // activation
__device__ float  g_sum[HID];
__device__ float  g_sumsq[HID];

// buffer ids: 0 = g_h4, 1 = g_agg4, 2 = g_act4, 3 = external
__device__ __forceinline__ const float4* pick_c4(int id, const float4* ext) {
    return id == 0 ? g_h4 : id == 1 ? g_agg4 : id == 2 ? g_act4 : ext;
}
__device__ __forceinline__ float4* pick_m4(int id, float4* ext) {
    return id == 0 ? g_h4 : id == 1 ? g_agg4 : id == 2 ? g_act4 : ext;
}

// ---------------- edge dtype detection ----------------
__global__ void k_detect_dtype(const int* __restrict__ ei32) {
    if (threadIdx.x == 0 && blockIdx.x == 0) {
        int nonzero = 0;
        for (int i = 0; i < 1024; i++)
            if (ei32[2 * i + 1] != 0) nonzero++;
        g_is64 = (nonzero == 0) ? 1 : 0;
    }
}

// ---------------- degree counting ----------------
__global__ void k_deg_init() {
    int i = blockIdx.x * blockDim.x + threadIdx.x;
    if (i < N_NODES) { g_deg[i] = 1.0f; g_cnt[i] = 0; }
}

__global__ void k_deg_count(const void* __restrict__ ei) {
    int e = blockIdx.x * blockDim.x + threadIdx.x;
    if (e >= N_EDGES) return;
    int s, d;
    if (g_is64) {
        const long long* p = (const long long*)ei;
        s = (int)p[e];
        d = (int)p[N_EDGES + e];
    } else {
        const int* p = (const int*)ei;
        s = p[e];
        d = p[N_EDGES + e];
    }
    if (s < 0 || s >= N_NODES) s = 0;
    if (d < 0 || d >= N_NODES) d = 0;
    g_srcb[e] = s;
    g_dstb[e] = d;
    atomicAdd(&g_deg[d], 1.0f);
    atomicAdd(&g_cnt[d], 1);
}

__global__ void k_dinv() {
    int i = blockIdx.x * blockDim.x + threadIdx.x;
    if (i < N_NODES) g_dinv[i] = rsqrtf(g_deg[i]);
}

// ---------------- prefix scan ----------------
__global__ void k_scan1() {
    __shared__ int wsum[8];
    int i = blockIdx.x * 256 + threadIdx.x;
    int lane = threadIdx.x & 31;
    int wid = threadIdx.x >> 5;
    int v = (i < N_NODES) ? g_cnt[i] : 0;
#pragma unroll
    for (int o = 1; o < 32; o <<= 1) {
        int n = __shfl_up_sync(0xFFFFFFFFu, v, o);
        if (lane >= o) v += n;
    }
    if (lane == 31) wsum[wid] = v;
    __syncthreads();
    if (wid == 0) {
        int w = (lane < 8) ? wsum[lane] : 0;
#pragma unroll
        for (int o = 1; o < 8; o <<= 1) {
            int n = __shfl_up_sync(0xFFFFFFFFu, w, o);
            if (lane >= o) w += n;
        }
        if (lane < 8) wsum[lane] = w;
    }
    __syncthreads();
    if (wid > 0) v += wsum[wid - 1];
    if (i < N_NODES) g_scan[i] = v;
    if (threadIdx.x == 255) g_bsum[blockIdx.x] = v;
}

__global__ void k_scan2() {
    __shared__ int s[NBLK_SCAN];
    int t = threadIdx.x;
    if (t < NBLK_SCAN) s[t] = g_bsum[t];
    __syncthreads();
    if (t == 0) {
        int run = 0;
        for (int b = 0; b < NBLK_SCAN; b++) {
            g_boff[b] = run;
            run += s[b];
        }
    }
}

__global__ void k_scan3() {
    int i = blockIdx.x * 256 + threadIdx.x;
    if (i >= N_NODES) return;
    int rs = g_boff[blockIdx.x] + g_scan[i] - g_cnt[i];
    g_rowstart[i] = rs;
    g_cursor[i] = rs;
}

// ---------------- CSR build ----------------
__global__ void k_build_csr() {
    int e = blockIdx.x * blockDim.x + threadIdx.x;
    if (e >= N_EDGES) return;
    int s = g_srcb[e];
    int d = g_dstb[e];
    int pos = atomicAdd(&g_cursor[d], 1);
    g_csrc[pos] = s;
    g_cnorm[pos] = g_dinv[s] * g_dinv[d];
}

// ---------------- SGEMM: g_h = A[M,K] @ W[K,N] ----------------
// 128x128 tile, BK=16, 8x8/thread, 256 threads, double-buffered smem.
#define BM 128
#define BN 128
#define BK 16

__device__ __forceinline__ void ld_tile(const float* __restrict__ A,
                                        const float* __restrict__ W,
                                        int M, int K, int N,
                                        int block_row, int block_col, int k0,
                                        int tid, float4 ar[2], float4 br[2]) {
#pragma unroll
    for (int l = 0; l < 2; l++) {
        int id = l * 256 + tid;
        int row = id >> 2, cf4 = id & 3;
        int gr = block_row + row;
        ar[l] = make_float4(0.f, 0.f, 0.f, 0.f);
        if (gr < M) ar[l] = *(const float4*)(A + (size_t)gr * K + k0 + cf4 * 4);
        int brow = id >> 5, bf4 = id & 31;
        int gc = block_col + bf4 * 4;
        const float* wp = W + (size_t)(k0 + brow) * N;
        if (gc + 3 < N) {
            br[l] = *(const float4*)(wp + gc);
        } else {
            br[l].x = (gc + 0 < N) ? wp[gc + 0] : 0.f;
            br[l].y = (gc + 1 < N) ? wp[gc + 1] : 0.f;
            br[l].z = (gc + 2 < N) ? wp[gc + 2] : 0.f;
            br[l].w = (gc + 3 < N) ? wp[gc + 3] : 0.f;
        }
    }
}

__device__ __forceinline__ void st_tile(float As[BK][BM + 4], float Bs[BK][BN],
                                        int tid, const float4 ar[2], const float4 br[2]) {
#pragma unroll
    for (int l = 0; l < 2; l++) {
        int id = l * 256 + tid;
        int row = id >> 2, cf4 = id & 3;
        As[cf4 * 4 + 0][row] = ar[l].x;
        As[cf4 * 4 + 1][row] = ar[l].y;
        As[cf4 * 4 + 2][row] = ar[l].z;
        As[cf4 * 4 + 3][row] = ar[l].w;
        int brow = id >> 5, bf4 = id & 31;
        *(float4*)&Bs[brow][bf4 * 4] = br[l];
    }
}

__global__ void __launch_bounds__(256) k_sgemm(
        const float* __restrict__ A_ext, int a_id,
        const float* __restrict__ W, int M, int K, int N) {
    const float* A = (const float*)pick_c4(a_id, (const float4*)A_ext);
    float* C = (float*)g_h4;

    __shared__ float As[2][BK][BM + 4];
    __shared__ float Bs[2][BK][BN];

    const int tid = threadIdx.x;
    const int block_row = blockIdx.y * BM;
    const int block_col = blockIdx.x * BN;
    const int tx = tid % 16;
    const int ty = tid / 16;

    float acc[8][8];
#pragma unroll
    for (int i = 0; i < 8; i++)
#pragma unroll
        for (int j = 0; j < 8; j++) acc[i][j] = 0.0f;

    float4 ar[2], br[2];
    const int ntiles = K / BK;

    ld_tile(A, W, M, K, N, block_row, block_col, 0, tid, ar, br);
    st_tile(As[0], Bs[0], tid, ar, br);
    __syncthreads();

    for (int t = 0; t < ntiles; t++) {
        int cur = t & 1;
        if (t + 1 < ntiles)
            ld_tile(A, W, M, K, N, block_row, block_col, (t + 1) * BK, tid, ar, br);

#pragma unroll
        for (int k = 0; k < BK; k++) {
            float a[8], b[8];
            *(float4*)&a[0] = *(const float4*)&As[cur][k][ty * 8];
            *(float4*)&a[4] = *(const float4*)&As[cur][k][ty * 8 + 4];
            *(float4*)&b[0] = *(const float4*)&Bs[cur][k][tx * 8];
            *(float4*)&b[4] = *(const float4*)&Bs[cur][k][tx * 8 + 4];
#pragma unroll
            for (int i = 0; i < 8; i++)
#pragma unroll
                for (int j = 0; j < 8; j++)
                    acc[i][j] = fmaf(a[i], b[j], acc[i][j]);
        }

        if (t + 1 < ntiles) {
            st_tile(As[cur ^ 1], Bs[cur ^ 1], tid, ar, br);
            __syncthreads();
        }
    }

#pragma unroll
    for (int i = 0; i < 8; i++) {
        int r = block_row + ty * 8 + i;
        if (r >= M) continue;
#pragma unroll
        for (int j0 = 0; j0 < 8; j0 += 4) {
            int c = block_col + tx * 8 + j0;
            if (c + 3 < N) {
                *(float4*)(C + (size_t)r * N + c) =
                    make_float4(acc[i][j0], acc[i][j0 + 1], acc[i][j0 + 2], acc[i][j0 + 3]);
            } else {
#pragma unroll
                for (int j = 0; j < 4; j++)
                    if (c + j < N) C[(size_t)r * N + c + j] = acc[i][j0 + j];
            }
        }
    }
}

// ---------------- CSR aggregation (fused self-loop, no bias, no atomics) ----
// one warp per dst node; lane l covers float4 columns {l, l+32, l+64, l+96}
__global__ void k_agg_csr(const float4* __restrict__ in_ext, int in_id,
                          float4* __restrict__ out_ext, int out_id, int O) {
    int wg = (blockIdx.x * blockDim.x + threadIdx.x) >> 5;
    int lane = threadIdx.x & 31;
    if (wg >= N_NODES) return;
    const float4* in = pick_c4(in_id, in_ext);
    float4* out = pick_m4(out_id, out_ext);
    const int d = wg;
    const int nv = O >> 2;
    const float di = g_dinv[d];
    const float sc = di * di;
    const int start = g_rowstart[d];
    const int cnt = g_cnt[d];

    float4 acc[4];
#pragma unroll
    for (int a = 0; a < 4; a++) {
        int f = lane + a * 32;
        if (f < nv) {
            float4 h = in[(size_t)d * nv + f];
            acc[a] = make_float4(h.x * sc, h.y * sc, h.z * sc, h.w * sc);
        }
    }
    for (int j = 0; j < cnt; j++) {
        int s = g_csrc[start + j];
        float w = g_cnorm[start + j];
        const float4* hs = in + (size_t)s * nv;
#pragma unroll
        for (int a = 0; a < 4; a++) {
            int f = lane + a * 32;
            if (f < nv) {
                float4 v = hs[f];
                acc[a].x = fmaf(v.x, w, acc[a].x);
                acc[a].y = fmaf(v.y, w, acc[a].y);
                acc[a].z = fmaf(v.z, w, acc[a].z);
                acc[a].w = fmaf(v.w, w, acc[a].w);
            }
        }
    }
    float4* op = out + (size_t)d * nv;
#pragma unroll
    for (int a = 0; a < 4; a++) {
        int f = lane + a * 32;
        if (f < nv) op[f] = acc[a];
    }
}

// ---------------- batch norm ----------------
__global__ void k_zero_sums(int O) {
    int c = blockIdx.x * blockDim.x + threadIdx.x;
    if (c < O) { g_sum[c] = 0.0f; g_sumsq[c] = 0.0f; }
}

__global__ void k_bn_reduce(int src_id, int O) {
    int c = blockIdx.x * blockDim.x + threadIdx.x;
    if (c >= O) return;
    const float* src = (const float*)pick_c4(src_id, nullptr);
    float s = 0.0f, ss = 0.0f;
    for (int r = blockIdx.y; r < N_NODES; r += gridDim.y) {
        float v = src[(size_t)r * O + c];
        s += v;
        ss += v * v;
    }
    atomicAdd(&g_sum[c], s);
    atomicAdd(&g_sumsq[c], ss);
}

__global__ void k_bn_apply(int src_id, float* __restrict__ y_ext, int dst_id,
                           const float* __restrict__ gamma,
                           const float* __restrict__ beta,
                           int O, int do_relu) {
    const float4* src = pick_c4(src_id, nullptr);
    float4* y = pick_m4(dst_id, (float4*)y_ext);
    int nv = O >> 2;
    size_t idx = (size_t)blockIdx.x * blockDim.x + threadIdx.x;
    size_t total = (size_t)N_NODES * nv;
    if (idx >= total) return;
    int f4 = (int)(idx % nv);
    int c = f4 * 4;
    float4 v = src[idx];
    float4 r;
    const float inv_n = 1.0f / N_NODES;
#pragma unroll
    for (int j = 0; j < 4; j++) {
        float mu = g_sum[c + j] * inv_n;
        float var = g_sumsq[c + j] * inv_n - mu * mu;
        float* vp = (j == 0) ? &v.x : (j == 1) ? &v.y : (j == 2) ? &v.z : &v.w;
        float* rp = (j == 0) ? &r.x : (j == 1) ? &r.y : (j == 2) ? &r.z : &r.w;
        float o = gamma[c + j] * (*vp - mu) * rsqrtf(var + BN_EPS) + beta[c + j];
        if (do_relu) o = fmaxf(o, 0.0f);
        *rp = o;
    }
    y[idx] = r;
}

// ---------------- launch ----------------
static inline int cdiv(long long a, long long b) { return (int)((a + b - 1) / b); }

extern "C" void kernel_launch(void* const* d_in, const int* in_sizes, int n_in,
                              void* d_out, int out_size) {
    const float* x = (const float*)d_in[0];
    const void* ei = d_in[1];
    const float* W1 = (const float*)d_in[2];
    const float* g1 = (const float*)d_in[4];
    const float* be1 = (const float*)d_in[5];
    const float* W2 = (const float*)d_in[6];
    const float* g2 = (const float*)d_in[8];
    const float* be2 = (const float*)d_in[9];
    const float* W3 = (const float*)d_in[10];
    const float* g3 = (const float*)d_in[12];
    const float* be3 = (const float*)d_in[13];
    // biases b1/b2/b3 are mathematically dead: BN(h+b) == BN(h)

    float* out_logits = (float*)d_out;                        // [N, 40]
    float* out_x6 = (float*)d_out + (size_t)N_NODES * N_CLS;  // [N, 512]

    const int T = 256;

    // preprocessing: dtype, degrees, CSR
    k_detect_dtype<<<1, 32>>>((const int*)ei);
    k_deg_init<<<cdiv(N_NODES, T), T>>>();
    k_deg_count<<<cdiv(N_EDGES, T), T>>>(ei);
    k_dinv<<<cdiv(N_NODES, T), T>>>();
    k_scan1<<<NBLK_SCAN, 256>>>();
    k_scan2<<<1, 512>>>();
    k_scan3<<<NBLK_SCAN, 256>>>();
    k_build_csr<<<cdiv(N_EDGES, T), T>>>();

    dim3 gemm_grid_h(HID / BN, cdiv(N_NODES, BM));     // (4, 782)
    dim3 gemm_grid_c(1, cdiv(N_NODES, BM));            // N=40

    size_t totH4 = (size_t)N_NODES * (HID / 4);
    size_t totC4 = (size_t)N_NODES * (N_CLS / 4);
    int agg_blocks = cdiv((long long)N_NODES * 32, T);

    // ---- Layer 1: agg(x) -> g_agg4 [N,128] ; @W1 -> g_h4 ; BN+ReLU -> g_act4
    k_agg_csr<<<agg_blocks, T>>>((const float4*)x, 3, nullptr, 1, F_IN);
    k_sgemm<<<gemm_grid_h, T>>>(nullptr, 1, W1, N_NODES, F_IN, HID);
    k_zero_sums<<<cdiv(HID, T), T>>>(HID);
    { dim3 rg(cdiv(HID, T), 128); k_bn_reduce<<<rg, T>>>(0, HID); }
    k_bn_apply<<<cdiv(totH4, T), T>>>(0, nullptr, 2, g1, be1, HID, 1);

    // ---- Layer 2: g_act4 @ W2 -> g_h4 ; agg -> g_agg4 ; BN+ReLU -> x6
    k_sgemm<<<gemm_grid_h, T>>>(nullptr, 2, W2, N_NODES, HID, HID);
    k_agg_csr<<<agg_blocks, T>>>(nullptr, 0, nullptr, 1, HID);
    k_zero_sums<<<cdiv(HID, T), T>>>(HID);
    { dim3 rg(cdiv(HID, T), 128); k_bn_reduce<<<rg, T>>>(1, HID); }
    k_bn_apply<<<cdiv(totH4, T), T>>>(1, out_x6, 3, g2, be2, HID, 1);

    // ---- Layer 3: x6 @ W3 -> g_h4[:, :40] ; agg -> g_agg4 ; BN -> logits
    k_sgemm<<<gemm_grid_c, T>>>(out_x6, 3, W3, N_NODES, HID, N_CLS);
    k_agg_csr<<<agg_blocks, T>>>(nullptr, 0, nullptr, 1, N_CLS);
    k_zero_sums<<<cdiv(N_CLS, T), T>>>(N_CLS);
    { dim3 rg(cdiv(N_CLS, T), 128); k_bn_reduce<<<rg, T>>>(1, N_CLS); }
    k_bn_apply<<<cdiv(totC4, T), T>>>(1, out_logits, 3, g3, be3, N_CLS, 0);
}